// round 2
// baseline (speedup 1.0000x reference)
#include <cuda_runtime.h>

#define NN   50000
#define INF  128
#define HF   256
#define NE   800000
#define KTOT 256          // concat K for layer-1 GEMM

// ---------------- scratch (static device globals; no allocation) -------------
__device__ int   d_is64;
__device__ int   d_deg[NN];
__device__ int   d_rowptr[NN + 1];
__device__ int   d_cursor[NN];
__device__ int   d_csrc[NE];
__device__ __align__(16) float d_A[NN * KTOT];   // [agg1 | x]  N x 256
__device__ __align__(16) float d_h[NN * HF];     // hidden      N x 256
__device__ float d_p[NN];          // h . W2_l
__device__ float d_q[NN];          // h . W2_r
__device__ int   d_bsum[64];
__device__ int   d_boff[64];

// edge_index may be int32 or int64 depending on how the reference materialized
// it (JAX silently downgrades int64 -> int32 without x64). Detect at runtime:
// for true int64 with values < 2^31, every odd int32 word is 0.
__global__ void k_detect(const int* __restrict__ ei32) {
    if (threadIdx.x == 0 && blockIdx.x == 0) {
        int all0 = 1;
        for (int i = 0; i < 32; i++)
            if (ei32[2 * i + 1] != 0) { all0 = 0; break; }
        d_is64 = all0;
    }
}

__device__ __forceinline__ int edge_at(const void* ei, long long idx) {
    if (d_is64) return (int)((const long long*)ei)[idx];
    return ((const int*)ei)[idx];
}

// ---------------- CSR build --------------------------------------------------
__global__ void k_zero_deg() {
    int i = blockIdx.x * blockDim.x + threadIdx.x;
    if (i < NN) d_deg[i] = 0;
}

__global__ void k_count(const void* __restrict__ ei) {
    int e = blockIdx.x * blockDim.x + threadIdx.x;
    if (e < NE) {
        int dst = edge_at(ei, (long long)NE + e);
        if ((unsigned)dst < NN) atomicAdd(&d_deg[dst], 1);
    }
}

// block-local exclusive scan: 256 threads x 4 elems = 1024 per block, 49 blocks
__global__ void k_scan1() {
    __shared__ int sh[256];
    int t = threadIdx.x;
    int base = blockIdx.x * 1024 + t * 4;
    int v[4];
#pragma unroll
    for (int i = 0; i < 4; i++) {
        int idx = base + i;
        v[i] = (idx < NN) ? d_deg[idx] : 0;
    }
    int s = v[0] + v[1] + v[2] + v[3];
    sh[t] = s;
    __syncthreads();
    for (int off = 1; off < 256; off <<= 1) {
        int x_ = (t >= off) ? sh[t - off] : 0;
        __syncthreads();
        sh[t] += x_;
        __syncthreads();
    }
    int run = sh[t] - s;   // exclusive offset within block
#pragma unroll
    for (int i = 0; i < 4; i++) {
        int idx = base + i;
        if (idx < NN) d_rowptr[idx] = run;
        run += v[i];
    }
    if (t == 255) d_bsum[blockIdx.x] = sh[255];
}

__global__ void k_scan2(int nb) {
    if (threadIdx.x == 0) {
        int run = 0;
        for (int b = 0; b < nb; b++) {
            d_boff[b] = run;
            run += d_bsum[b];
        }
    }
}

__global__ void k_scan3() {
    int i = blockIdx.x * blockDim.x + threadIdx.x;
    if (i < NN) {
        int r = d_rowptr[i] + d_boff[i >> 10];
        d_rowptr[i] = r;
        d_cursor[i] = r;
    }
    if (i == 0) d_rowptr[NN] = NE;
}

__global__ void k_fill(const void* __restrict__ ei) {
    int e = blockIdx.x * blockDim.x + threadIdx.x;
    if (e < NE) {
        int dst = edge_at(ei, (long long)NE + e);
        int src = edge_at(ei, e);
        if ((unsigned)dst < NN && (unsigned)src < NN) {
            int pos = atomicAdd(&d_cursor[dst], 1);
            if ((unsigned)pos < NE) d_csrc[pos] = src;
        }
    }
}

// ---------------- aggregation 1 (warp per node) + pack A = [agg1 | x] --------
__global__ void k_agg1(const float* __restrict__ x) {
    int warp = threadIdx.x >> 5;
    int lane = threadIdx.x & 31;
    int n = blockIdx.x * 8 + warp;
    if (n >= NN) return;

    int s = d_rowptr[n], e = d_rowptr[n + 1];
    float4 acc = make_float4(0.f, 0.f, 0.f, 0.f);
    for (int j = s; j < e; j++) {
        int src = d_csrc[j];
        float4 v = reinterpret_cast<const float4*>(x + (size_t)src * INF)[lane];
        acc.x += v.x; acc.y += v.y; acc.z += v.z; acc.w += v.w;
    }
    int deg = e - s;
    float inv = 1.f / (float)max(deg, 1);
    acc.x *= inv; acc.y *= inv; acc.z *= inv; acc.w *= inv;

    float4* Arow = reinterpret_cast<float4*>(d_A + (size_t)n * KTOT);
    Arow[lane] = acc;                                            // cols 0..127
    Arow[32 + lane] = reinterpret_cast<const float4*>(x + (size_t)n * INF)[lane]; // 128..255
}

// ---------------- GEMM: h = relu(A[N,256] @ Wcat[256,256]^T + b1) ------------
// BM=128, BN=128, KT=32; 256 threads; 8x8 per thread.
__global__ void __launch_bounds__(256)
k_gemm(const float* __restrict__ W1l, const float* __restrict__ W1r,
       const float* __restrict__ b1) {
    __shared__ __align__(16) float As[32][128];      // [k][row]
    __shared__ __align__(16) float Bs[32][132];      // [k][col] (pad: 132*4=528, 16B-aligned rows)

    int t = threadIdx.x;
    int tx = t & 15;          // col group
    int ty = t >> 4;          // row group
    int rowbase = blockIdx.x * 128;
    int colbase = blockIdx.y * 128;

    float acc[8][8];
#pragma unroll
    for (int i = 0; i < 8; i++)
#pragma unroll
        for (int j = 0; j < 8; j++) acc[i][j] = 0.f;

    for (int kt = 0; kt < 8; kt++) {
        int k0 = kt * 32;
        // load B tile (transpose W rows into [k][col])
        const float* Wb = (k0 < 128) ? W1l : W1r;
        int kk0 = k0 & 127;
#pragma unroll
        for (int i = 0; i < 4; i++) {
            int l = t * 4 + i;
            int c = l >> 3;
            int f4 = l & 7;
            float4 w = reinterpret_cast<const float4*>(
                Wb + (size_t)(colbase + c) * 128 + kk0 + f4 * 4)[0];
            Bs[f4 * 4 + 0][c] = w.x;
            Bs[f4 * 4 + 1][c] = w.y;
            Bs[f4 * 4 + 2][c] = w.z;
            Bs[f4 * 4 + 3][c] = w.w;
        }
        // load A tile
#pragma unroll
        for (int i = 0; i < 4; i++) {
            int l = t * 4 + i;
            int r = l >> 3;
            int f4 = l & 7;
            int gr = rowbase + r;
            float4 a = make_float4(0.f, 0.f, 0.f, 0.f);
            if (gr < NN)
                a = reinterpret_cast<const float4*>(
                    d_A + (size_t)gr * KTOT + k0 + f4 * 4)[0];
            As[f4 * 4 + 0][r] = a.x;
            As[f4 * 4 + 1][r] = a.y;
            As[f4 * 4 + 2][r] = a.z;
            As[f4 * 4 + 3][r] = a.w;
        }
        __syncthreads();

#pragma unroll
        for (int kk = 0; kk < 32; kk++) {
            float4 a0 = *reinterpret_cast<float4*>(&As[kk][ty * 8]);
            float4 a1 = *reinterpret_cast<float4*>(&As[kk][ty * 8 + 4]);
            float4 b0 = *reinterpret_cast<float4*>(&Bs[kk][tx * 8]);
            float4 b1v = *reinterpret_cast<float4*>(&Bs[kk][tx * 8 + 4]);
            float ar[8] = {a0.x, a0.y, a0.z, a0.w, a1.x, a1.y, a1.z, a1.w};
            float br[8] = {b0.x, b0.y, b0.z, b0.w, b1v.x, b1v.y, b1v.z, b1v.w};
#pragma unroll
            for (int i = 0; i < 8; i++)
#pragma unroll
                for (int j = 0; j < 8; j++)
                    acc[i][j] = fmaf(ar[i], br[j], acc[i][j]);
        }
        __syncthreads();
    }

    // epilogue: + bias, relu, store h
#pragma unroll
    for (int i = 0; i < 8; i++) {
        int gr = rowbase + ty * 8 + i;
        if (gr >= NN) continue;
#pragma unroll
        for (int j = 0; j < 8; j++) {
            int gc = colbase + tx * 8 + j;
            float v = acc[i][j] + b1[gc];
            d_h[(size_t)gr * HF + gc] = v > 0.f ? v : 0.f;
        }
    }
}

// ---------------- p = h.W2_l, q = h.W2_r (warp per node) ---------------------
__global__ void k_pq(const float* __restrict__ W2l, const float* __restrict__ W2r) {
    int warp = threadIdx.x >> 5;
    int lane = threadIdx.x & 31;
    int n = blockIdx.x * 8 + warp;
    if (n >= NN) return;

    const float4* hr = reinterpret_cast<const float4*>(d_h + (size_t)n * HF);
    const float4* wl = reinterpret_cast<const float4*>(W2l);
    const float4* wr = reinterpret_cast<const float4*>(W2r);
    float p = 0.f, q = 0.f;
#pragma unroll
    for (int i = 0; i < 2; i++) {
        float4 h4 = hr[lane * 2 + i];
        float4 l4 = wl[lane * 2 + i];
        float4 r4 = wr[lane * 2 + i];
        p += h4.x * l4.x + h4.y * l4.y + h4.z * l4.z + h4.w * l4.w;
        q += h4.x * r4.x + h4.y * r4.y + h4.z * r4.z + h4.w * r4.w;
    }
#pragma unroll
    for (int off = 16; off > 0; off >>= 1) {
        p += __shfl_down_sync(0xffffffffu, p, off);
        q += __shfl_down_sync(0xffffffffu, q, off);
    }
    if (lane == 0) { d_p[n] = p; d_q[n] = q; }
}

// ---------------- out = mean_agg(p) + b2 + q (warp per node) -----------------
__global__ void k_out(const float* __restrict__ b2, float* __restrict__ out) {
    int warp = threadIdx.x >> 5;
    int lane = threadIdx.x & 31;
    int n = blockIdx.x * 8 + warp;
    if (n >= NN) return;

    int s = d_rowptr[n], e = d_rowptr[n + 1];
    float acc = 0.f;
    for (int j = s + lane; j < e; j += 32) acc += d_p[d_csrc[j]];
#pragma unroll
    for (int off = 16; off > 0; off >>= 1)
        acc += __shfl_down_sync(0xffffffffu, acc, off);
    if (lane == 0) {
        int deg = e - s;
        out[n] = acc / (float)max(deg, 1) + b2[0] + d_q[n];
    }
}

// ---------------- launch -----------------------------------------------------
extern "C" void kernel_launch(void* const* d_in, const int* in_sizes, int n_in,
                              void* d_out, int out_size) {
    const float* x    = (const float*)d_in[0];
    const void*  ei   = d_in[1];               // int32 or int64, detected on device
    const float* W1l  = (const float*)d_in[2];
    const float* b1   = (const float*)d_in[3];
    const float* W1r  = (const float*)d_in[4];
    const float* W2l  = (const float*)d_in[5];
    const float* b2   = (const float*)d_in[6];
    const float* W2r  = (const float*)d_in[7];
    float* out = (float*)d_out;

    const int nb_scan = (NN + 1023) / 1024;   // 49

    k_detect<<<1, 32>>>((const int*)ei);
    k_zero_deg<<<(NN + 255) / 256, 256>>>();
    k_count<<<(NE + 255) / 256, 256>>>(ei);
    k_scan1<<<nb_scan, 256>>>();
    k_scan2<<<1, 32>>>(nb_scan);
    k_scan3<<<(NN + 255) / 256, 256>>>();
    k_fill<<<(NE + 255) / 256, 256>>>(ei);

    k_agg1<<<(NN + 7) / 8, 256>>>(x);

    dim3 ggrid((NN + 127) / 128, 2);
    k_gemm<<<ggrid, 256>>>(W1l, W1r, b1);

    k_pq<<<(NN + 7) / 8, 256>>>(W2l, W2r);
    k_out<<<(NN + 7) / 8, 256>>>(b2, out);
}

// round 4
// speedup vs baseline: 1.8889x; 1.8889x over previous
#include <cuda_runtime.h>
#include <cuda_bf16.h>
#include <cstdint>

#define NN   50000
#define INF  128
#define HF   256
#define NE   800000
#define KTOT 256

// ---------------- scratch (static device globals; no allocation) -------------
__device__ int   d_is64;
__device__ int   d_deg[NN];
__device__ int   d_rowptr[NN + 1];
__device__ int   d_cursor[NN];
__device__ int   d_csrc[NE];
__device__ __align__(16) __nv_bfloat16 d_Ahi[NN * KTOT];  // [agg1 | x] hi
__device__ __align__(16) __nv_bfloat16 d_Alo[NN * KTOT];  // [agg1 | x] lo
__device__ __align__(16) __nv_bfloat16 d_Whi[HF * KTOT];  // Wcat hi  (n-major, k contig)
__device__ __align__(16) __nv_bfloat16 d_Wlo[HF * KTOT];  // Wcat lo
__device__ float d_p[NN];
__device__ float d_q[NN];
__device__ int   d_bsum[64];
__device__ int   d_boff[64];

// ---------------- dtype detect ----------------------------------------------
__global__ void k_detect(const int* __restrict__ ei32) {
    if (threadIdx.x == 0 && blockIdx.x == 0) {
        int all0 = 1;
        for (int i = 0; i < 32; i++)
            if (ei32[2 * i + 1] != 0) { all0 = 0; break; }
        d_is64 = all0;
    }
}
__device__ __forceinline__ int edge_at(const void* ei, long long idx) {
    if (d_is64) return (int)((const long long*)ei)[idx];
    return ((const int*)ei)[idx];
}

// ---------------- CSR build --------------------------------------------------
__global__ void k_zero_deg() {
    int i = blockIdx.x * blockDim.x + threadIdx.x;
    if (i < NN) d_deg[i] = 0;
}
__global__ void k_count(const void* __restrict__ ei) {
    int e = blockIdx.x * blockDim.x + threadIdx.x;
    if (e < NE) {
        int dst = edge_at(ei, (long long)NE + e);
        if ((unsigned)dst < NN) atomicAdd(&d_deg[dst], 1);
    }
}
__global__ void k_scan1() {
    __shared__ int sh[256];
    int t = threadIdx.x;
    int base = blockIdx.x * 1024 + t * 4;
    int v[4];
#pragma unroll
    for (int i = 0; i < 4; i++) {
        int idx = base + i;
        v[i] = (idx < NN) ? d_deg[idx] : 0;
    }
    int s = v[0] + v[1] + v[2] + v[3];
    sh[t] = s;
    __syncthreads();
    for (int off = 1; off < 256; off <<= 1) {
        int x_ = (t >= off) ? sh[t - off] : 0;
        __syncthreads();
        sh[t] += x_;
        __syncthreads();
    }
    int run = sh[t] - s;
#pragma unroll
    for (int i = 0; i < 4; i++) {
        int idx = base + i;
        if (idx < NN) d_rowptr[idx] = run;
        run += v[i];
    }
    if (t == 255) d_bsum[blockIdx.x] = sh[255];
}
__global__ void k_scan2(int nb) {
    if (threadIdx.x == 0) {
        int run = 0;
        for (int b = 0; b < nb; b++) { d_boff[b] = run; run += d_bsum[b]; }
    }
}
__global__ void k_scan3() {
    int i = blockIdx.x * blockDim.x + threadIdx.x;
    if (i < NN) {
        int r = d_rowptr[i] + d_boff[i >> 10];
        d_rowptr[i] = r;
        d_cursor[i] = r;
    }
    if (i == 0) d_rowptr[NN] = NE;
}
__global__ void k_fill(const void* __restrict__ ei) {
    int e = blockIdx.x * blockDim.x + threadIdx.x;
    if (e < NE) {
        int dst = edge_at(ei, (long long)NE + e);
        int src = edge_at(ei, e);
        if ((unsigned)dst < NN && (unsigned)src < NN) {
            int pos = atomicAdd(&d_cursor[dst], 1);
            if ((unsigned)pos < NE) d_csrc[pos] = src;
        }
    }
}

// ---------------- bf16 hi/lo split helpers -----------------------------------
__device__ __forceinline__ void cvt4(float4 v, uint2& hi, uint2& lo) {
    __nv_bfloat16 h0 = __float2bfloat16(v.x), h1 = __float2bfloat16(v.y),
                  h2 = __float2bfloat16(v.z), h3 = __float2bfloat16(v.w);
    __nv_bfloat16 l0 = __float2bfloat16(v.x - __bfloat162float(h0));
    __nv_bfloat16 l1 = __float2bfloat16(v.y - __bfloat162float(h1));
    __nv_bfloat16 l2 = __float2bfloat16(v.z - __bfloat162float(h2));
    __nv_bfloat16 l3 = __float2bfloat16(v.w - __bfloat162float(h3));
    hi.x = (uint32_t)__bfloat16_as_ushort(h0) | ((uint32_t)__bfloat16_as_ushort(h1) << 16);
    hi.y = (uint32_t)__bfloat16_as_ushort(h2) | ((uint32_t)__bfloat16_as_ushort(h3) << 16);
    lo.x = (uint32_t)__bfloat16_as_ushort(l0) | ((uint32_t)__bfloat16_as_ushort(l1) << 16);
    lo.y = (uint32_t)__bfloat16_as_ushort(l2) | ((uint32_t)__bfloat16_as_ushort(l3) << 16);
}

// ---------------- aggregation 1 + pack A=[agg1|x] as bf16 hi/lo --------------
__global__ void k_agg1(const float* __restrict__ x) {
    int warp = threadIdx.x >> 5;
    int lane = threadIdx.x & 31;
    int n = blockIdx.x * 8 + warp;
    if (n >= NN) return;

    int s = d_rowptr[n], e = d_rowptr[n + 1];
    float4 acc = make_float4(0.f, 0.f, 0.f, 0.f);
    for (int j = s; j < e; j++) {
        int src = d_csrc[j];
        float4 v = reinterpret_cast<const float4*>(x + (size_t)src * INF)[lane];
        acc.x += v.x; acc.y += v.y; acc.z += v.z; acc.w += v.w;
    }
    int deg = e - s;
    float inv = 1.f / (float)max(deg, 1);
    acc.x *= inv; acc.y *= inv; acc.z *= inv; acc.w *= inv;

    uint2 hi, lo;
    cvt4(acc, hi, lo);
    size_t rb = (size_t)n * KTOT;
    reinterpret_cast<uint2*>(d_Ahi + rb)[lane] = hi;        // cols lane*4 (agg)
    reinterpret_cast<uint2*>(d_Alo + rb)[lane] = lo;
    float4 xv = reinterpret_cast<const float4*>(x + (size_t)n * INF)[lane];
    cvt4(xv, hi, lo);
    reinterpret_cast<uint2*>(d_Ahi + rb + 128)[lane] = hi;  // cols 128+lane*4 (x)
    reinterpret_cast<uint2*>(d_Alo + rb + 128)[lane] = lo;
}

// ---------------- weight prep: Wcat -> bf16 hi/lo, n-major k-contig ----------
__global__ void k_wprep(const float* __restrict__ W1l, const float* __restrict__ W1r) {
    int t = blockIdx.x * blockDim.x + threadIdx.x;   // 65536
    if (t >= HF * KTOT) return;
    int n = t >> 8, k = t & 255;
    float w = (k < 128) ? W1l[n * 128 + k] : W1r[n * 128 + (k - 128)];
    __nv_bfloat16 h = __float2bfloat16(w);
    __nv_bfloat16 l = __float2bfloat16(w - __bfloat162float(h));
    d_Whi[t] = h;
    d_Wlo[t] = l;
}

// ---------------- mma.sync bf16 GEMM + fused p/q epilogue --------------------
// h = relu(A[N,256] @ Wcat[256,256]^T + b1); p = h.W2l; q = h.W2r (h not stored)
// CTA: 256 thr = 8 warps (4 M-stripes x 2 N-halves). BM=64, BN=256, K chunk 64.
// bf16 3-term split: Ahi*Bhi + Ahi*Blo + Alo*Bhi.
// smem rows padded to 72 bf16 (144B) -> conflict-free fragment loads.
#define APAD 72
#define SM_BIAS 0
#define SM_W2L  1024
#define SM_W2R  2048
#define SM_PQ   3072          // pbuf[2][64] (512B) + qbuf[2][64] (512B)
#define SM_AHI  4096          // 64*144 = 9216
#define SM_ALO  13312
#define SM_BHI  22528         // 256*144 = 36864
#define SM_BLO  59392
#define SM_TOT  96256

__device__ __forceinline__ void mma16816(float* c, uint32_t a0, uint32_t a1,
                                         uint32_t a2, uint32_t a3,
                                         uint32_t b0, uint32_t b1) {
    asm volatile(
        "mma.sync.aligned.m16n8k16.row.col.f32.bf16.bf16.f32 "
        "{%0,%1,%2,%3},{%4,%5,%6,%7},{%8,%9},{%0,%1,%2,%3};"
        : "+f"(c[0]), "+f"(c[1]), "+f"(c[2]), "+f"(c[3])
        : "r"(a0), "r"(a1), "r"(a2), "r"(a3), "r"(b0), "r"(b1));
}

__global__ void __launch_bounds__(256, 2)
k_gemm_mma(const float* __restrict__ b1, const float* __restrict__ W2l,
           const float* __restrict__ W2r) {
    extern __shared__ char smem[];
    int t = threadIdx.x;
    int wid = t >> 5;
    int lane = t & 31;
    int g = lane >> 2;        // group row 0..7
    int tq = lane & 3;        // quad thread 0..3
    int wm = wid & 3;         // M stripe (16 rows each)
    int wn = wid >> 2;        // N half (128 cols each)
    int rowbase = blockIdx.x * 64;

    // stage bias / W2 into smem
    *reinterpret_cast<float*>(smem + SM_BIAS + t * 4) = b1[t];
    *reinterpret_cast<float*>(smem + SM_W2L + t * 4) = W2l[t];
    *reinterpret_cast<float*>(smem + SM_W2R + t * 4) = W2r[t];

    float acc[64];
#pragma unroll
    for (int i = 0; i < 64; i++) acc[i] = 0.f;

    for (int ch = 0; ch < 4; ch++) {
        int kbase = ch * 64;
        __syncthreads();
        // --- stage A chunk: 64 rows x 64 k (hi+lo), 512 uint4 each ---
#pragma unroll
        for (int i = 0; i < 2; i++) {
            int v = t + i * 256;
            int row = v >> 3, kg = v & 7;
            int gr = rowbase + row;
            uint4 z = make_uint4(0, 0, 0, 0);
            uint4 a = (gr < NN)
                ? *reinterpret_cast<const uint4*>(d_Ahi + (size_t)gr * KTOT + kbase + kg * 8) : z;
            *reinterpret_cast<uint4*>(smem + SM_AHI + row * 144 + kg * 16) = a;
            uint4 b = (gr < NN)
                ? *reinterpret_cast<const uint4*>(d_Alo + (size_t)gr * KTOT + kbase + kg * 8) : z;
            *reinterpret_cast<uint4*>(smem + SM_ALO + row * 144 + kg * 16) = b;
        }
        // --- stage B chunk: 256 n-rows x 64 k (hi+lo), 2048 uint4 each ---
#pragma unroll
        for (int i = 0; i < 8; i++) {
            int v = t + i * 256;
            int row = v >> 3, kg = v & 7;
            uint4 a = *reinterpret_cast<const uint4*>(d_Whi + (size_t)row * KTOT + kbase + kg * 8);
            *reinterpret_cast<uint4*>(smem + SM_BHI + row * 144 + kg * 16) = a;
            uint4 b = *reinterpret_cast<const uint4*>(d_Wlo + (size_t)row * KTOT + kbase + kg * 8);
            *reinterpret_cast<uint4*>(smem + SM_BLO + row * 144 + kg * 16) = b;
        }
        __syncthreads();

#pragma unroll
        for (int ks = 0; ks < 4; ks++) {
            int k0 = ks * 16;
            int arow = wm * 16 + g;
            int koff = (k0 + 2 * tq) * 2;   // byte offset of k element pair
            // A fragments (hi and lo)
            uint32_t ah0 = *reinterpret_cast<const uint32_t*>(smem + SM_AHI + arow * 144 + koff);
            uint32_t ah1 = *reinterpret_cast<const uint32_t*>(smem + SM_AHI + (arow + 8) * 144 + koff);
            uint32_t ah2 = *reinterpret_cast<const uint32_t*>(smem + SM_AHI + arow * 144 + koff + 16);
            uint32_t ah3 = *reinterpret_cast<const uint32_t*>(smem + SM_AHI + (arow + 8) * 144 + koff + 16);
            uint32_t al0 = *reinterpret_cast<const uint32_t*>(smem + SM_ALO + arow * 144 + koff);
            uint32_t al1 = *reinterpret_cast<const uint32_t*>(smem + SM_ALO + (arow + 8) * 144 + koff);
            uint32_t al2 = *reinterpret_cast<const uint32_t*>(smem + SM_ALO + arow * 144 + koff + 16);
            uint32_t al3 = *reinterpret_cast<const uint32_t*>(smem + SM_ALO + (arow + 8) * 144 + koff + 16);
#pragma unroll
            for (int j = 0; j < 16; j++) {
                int n = wn * 128 + j * 8 + g;
                uint32_t bh0 = *reinterpret_cast<const uint32_t*>(smem + SM_BHI + n * 144 + koff);
                uint32_t bh1 = *reinterpret_cast<const uint32_t*>(smem + SM_BHI + n * 144 + koff + 16);
                uint32_t bl0 = *reinterpret_cast<const uint32_t*>(smem + SM_BLO + n * 144 + koff);
                uint32_t bl1 = *reinterpret_cast<const uint32_t*>(smem + SM_BLO + n * 144 + koff + 16);
                float* c = acc + j * 4;
                mma16816(c, ah0, ah1, ah2, ah3, bh0, bh1);   // hi*hi
                mma16816(c, ah0, ah1, ah2, ah3, bl0, bl1);   // hi*lo
                mma16816(c, al0, al1, al2, al3, bh0, bh1);   // lo*hi
            }
        }
    }
    __syncthreads();

    // --- fused epilogue: relu(acc + bias), dot with W2l/W2r ---
    const float* s_bias = reinterpret_cast<const float*>(smem + SM_BIAS);
    const float* s_w2l = reinterpret_cast<const float*>(smem + SM_W2L);
    const float* s_w2r = reinterpret_cast<const float*>(smem + SM_W2R);
    float p1 = 0.f, q1 = 0.f, p2 = 0.f, q2 = 0.f;
#pragma unroll
    for (int j = 0; j < 16; j++) {
        int c0 = wn * 128 + j * 8 + 2 * tq;
        float v00 = acc[j * 4 + 0] + s_bias[c0];
        float v01 = acc[j * 4 + 1] + s_bias[c0 + 1];
        float v10 = acc[j * 4 + 2] + s_bias[c0];
        float v11 = acc[j * 4 + 3] + s_bias[c0 + 1];
        v00 = v00 > 0.f ? v00 : 0.f;
        v01 = v01 > 0.f ? v01 : 0.f;
        v10 = v10 > 0.f ? v10 : 0.f;
        v11 = v11 > 0.f ? v11 : 0.f;
        p1 = fmaf(v00, s_w2l[c0], fmaf(v01, s_w2l[c0 + 1], p1));
        q1 = fmaf(v00, s_w2r[c0], fmaf(v01, s_w2r[c0 + 1], q1));
        p2 = fmaf(v10, s_w2l[c0], fmaf(v11, s_w2l[c0 + 1], p2));
        q2 = fmaf(v10, s_w2r[c0], fmaf(v11, s_w2r[c0 + 1], q2));
    }
    // quad reduce (lanes g*4..g*4+3 share rows)
#pragma unroll
    for (int off = 1; off < 4; off <<= 1) {
        p1 += __shfl_xor_sync(0xffffffffu, p1, off);
        q1 += __shfl_xor_sync(0xffffffffu, q1, off);
        p2 += __shfl_xor_sync(0xffffffffu, p2, off);
        q2 += __shfl_xor_sync(0xffffffffu, q2, off);
    }
    float* pbuf = reinterpret_cast<float*>(smem + SM_PQ);          // [2][64]
    float* qbuf = reinterpret_cast<float*>(smem + SM_PQ + 512);    // [2][64]
    if (tq == 0) {
        int r1 = wm * 16 + g;
        pbuf[wn * 64 + r1] = p1;
        qbuf[wn * 64 + r1] = q1;
        pbuf[wn * 64 + r1 + 8] = p2;
        qbuf[wn * 64 + r1 + 8] = q2;
    }
    __syncthreads();
    if (t < 64) {
        int gr = rowbase + t;
        if (gr < NN) {
            d_p[gr] = pbuf[t] + pbuf[64 + t];
            d_q[gr] = qbuf[t] + qbuf[64 + t];
        }
    }
}

// ---------------- out = mean_agg(p) + b2 + q (warp per node) -----------------
__global__ void k_out(const float* __restrict__ b2, float* __restrict__ out) {
    int warp = threadIdx.x >> 5;
    int lane = threadIdx.x & 31;
    int n = blockIdx.x * 8 + warp;
    if (n >= NN) return;

    int s = d_rowptr[n], e = d_rowptr[n + 1];
    float acc = 0.f;
    for (int j = s + lane; j < e; j += 32) acc += d_p[d_csrc[j]];
#pragma unroll
    for (int off = 16; off > 0; off >>= 1)
        acc += __shfl_down_sync(0xffffffffu, acc, off);
    if (lane == 0) {
        int deg = e - s;
        out[n] = acc / (float)max(deg, 1) + b2[0] + d_q[n];
    }
}

// ---------------- launch -----------------------------------------------------
extern "C" void kernel_launch(void* const* d_in, const int* in_sizes, int n_in,
                              void* d_out, int out_size) {
    const float* x    = (const float*)d_in[0];
    const void*  ei   = d_in[1];
    const float* W1l  = (const float*)d_in[2];
    const float* b1   = (const float*)d_in[3];
    const float* W1r  = (const float*)d_in[4];
    const float* W2l  = (const float*)d_in[5];
    const float* b2   = (const float*)d_in[6];
    const float* W2r  = (const float*)d_in[7];
    float* out = (float*)d_out;

    cudaFuncSetAttribute(k_gemm_mma, cudaFuncAttributeMaxDynamicSharedMemorySize, SM_TOT);

    const int nb_scan = (NN + 1023) / 1024;   // 49

    k_detect<<<1, 32>>>((const int*)ei);
    k_zero_deg<<<(NN + 255) / 256, 256>>>();
    k_count<<<(NE + 255) / 256, 256>>>(ei);
    k_scan1<<<nb_scan, 256>>>();
    k_scan2<<<1, 32>>>(nb_scan);
    k_scan3<<<(NN + 255) / 256, 256>>>();
    k_fill<<<(NE + 255) / 256, 256>>>(ei);

    k_wprep<<<(HF * KTOT + 255) / 256, 256>>>(W1l, W1r);
    k_agg1<<<(NN + 7) / 8, 256>>>(x);

    k_gemm_mma<<<(NN + 63) / 64, 256, SM_TOT>>>(b1, W2l, W2r);

    k_out<<<(NN + 7) / 8, 256>>>(b2, out);
}